// round 5
// baseline (speedup 1.0000x reference)
#include <cuda_runtime.h>
#include <math.h>

#define HWDIM 128
#define NSP   16384   // 128*128
#define BATCH 2
#define HEADS 4
#define NCHUNK 16     // s-chunks for attention partial reduction
#define CHUNK  1024   // NSP / NCHUNK
#define TS     128    // smem tile of s per inner iteration

// ---------------- scratch (static device memory; no allocations) ----------------
__device__ float g_w_qkv[384 * 128];          // full quaternion 1x1 qkv weight
__device__ float g_w_dw [384 * 384 * 9];      // full quaternion 3x3 dw weight
__device__ float g_w_po [128 * 128];          // full quaternion 1x1 po weight
__device__ float g_buf1[(size_t)BATCH * 384 * NSP];  // qkv1 out, later attn out (as [B,128,NSP])
__device__ float g_buf2[(size_t)BATCH * 384 * NSP];  // dw out (q|k|v)
__device__ float g_Gp [NCHUNK * BATCH * HEADS * 32 * 32]; // partial Gram
__device__ float g_qnp[NCHUNK * BATCH * HEADS * 32];      // partial sum q^2
__device__ float g_knp[NCHUNK * BATCH * HEADS * 32];      // partial sum k^2
__device__ float g_attn[BATCH * HEADS * 32 * 32];         // softmaxed attention

// Hamilton product block table: W[p-block][q-block] = sign * component
__constant__ int   c_cidx[16] = {0,1,2,3, 1,0,3,2, 2,3,0,1, 3,2,1,0};
__constant__ float c_sign[16] = {1,-1,-1,-1, 1,1,-1,1, 1,1,1,-1, 1,-1,1,1};

// ---------------- build full quaternion weight ----------------
__global__ void build_weight(const float* __restrict__ r, const float* __restrict__ i,
                             const float* __restrict__ j, const float* __restrict__ k,
                             float* __restrict__ W, int Po, int Pi, int KHW) {
    const float* comps[4] = {r, i, j, k};
    int total = 4 * Po * 4 * Pi * KHW;
    for (int idx = blockIdx.x * blockDim.x + threadIdx.x; idx < total;
         idx += gridDim.x * blockDim.x) {
        int o   = idx / (4 * Pi * KHW);
        int rem = idx % (4 * Pi * KHW);
        int c   = rem / KHW;
        int kk  = rem % KHW;
        int p = o / Po, q = c / Pi;
        int t = p * 4 + q;
        const float* src = comps[c_cidx[t]];
        W[idx] = c_sign[t] * src[((o % Po) * Pi + (c % Pi)) * KHW + kk];
    }
}

// ---------------- implicit-GEMM conv (KS=1 or 3, pad=PAD), NCHW ----------------
// C[m,n] = sum_k W[m,k] * im2col(in)[k,n] + bias[m]
// Tile: 64(m) x 64(n) x 16(k); 256 threads; 4x4 micro-tile.
template <int KS, int PAD>
__global__ void conv_gemm(const float* __restrict__ W, const float* __restrict__ in,
                          const float* __restrict__ bias, float* __restrict__ out,
                          int Cout, int Cin) {
    const int K = Cin * KS * KS;
    const int b = blockIdx.z;
    const int m0 = blockIdx.y * 64, n0 = blockIdx.x * 64;
    const float* inb = in + (size_t)b * Cin * NSP;

    __shared__ float As[16][64];
    __shared__ float Bs[16][64];

    const int tid = threadIdx.x;
    const int tx = tid & 15, ty = tid >> 4;
    const int ma = tid >> 2, ka = (tid & 3) * 4;   // A loader: 1 float4 per thread
    const int nb = tid & 63, kb0 = (tid >> 6) * 4; // B loader: 4 scalars per thread

    float acc[4][4] = {};

    for (int k0 = 0; k0 < K; k0 += 16) {
        // load A tile (weights), transposed into As[k][m]
        float4 av = *(const float4*)&W[(size_t)(m0 + ma) * K + k0 + ka];
        As[ka + 0][ma] = av.x; As[ka + 1][ma] = av.y;
        As[ka + 2][ma] = av.z; As[ka + 3][ma] = av.w;
        // load B tile (im2col on the fly)
        #pragma unroll
        for (int rr = 0; rr < 4; rr++) {
            int kbr = kb0 + rr;
            int kk = k0 + kbr;
            float v;
            if (KS == 1) {
                v = inb[(size_t)kk * NSP + n0 + nb];
            } else {
                int cch = kk / 9;
                int rem = kk - cch * 9;
                int ky = rem / 3, kx = rem - ky * 3;
                int n = n0 + nb;
                int y = n >> 7, x = n & 127;
                int iy = y + ky - PAD, ix = x + kx - PAD;
                v = (iy >= 0 && iy < HWDIM && ix >= 0 && ix < HWDIM)
                        ? inb[((size_t)cch * HWDIM + iy) * HWDIM + ix] : 0.f;
            }
            Bs[kbr][nb] = v;
        }
        __syncthreads();
        #pragma unroll
        for (int kk = 0; kk < 16; kk++) {
            float4 a  = *(const float4*)&As[kk][ty * 4];
            float4 bv = *(const float4*)&Bs[kk][tx * 4];
            float af[4] = {a.x, a.y, a.z, a.w};
            float bf[4] = {bv.x, bv.y, bv.z, bv.w};
            #pragma unroll
            for (int im = 0; im < 4; im++)
                #pragma unroll
                for (int in_ = 0; in_ < 4; in_++)
                    acc[im][in_] += af[im] * bf[in_];
        }
        __syncthreads();
    }

    float* outb = out + (size_t)b * Cout * NSP;
    #pragma unroll
    for (int im = 0; im < 4; im++) {
        int m = m0 + ty * 4 + im;
        float bs = bias[m];
        #pragma unroll
        for (int in_ = 0; in_ < 4; in_++)
            outb[(size_t)m * NSP + n0 + tx * 4 + in_] = acc[im][in_] + bs;
    }
}

// ---------------- attention stage 1: partial Gram + norms (deterministic) ------
// grid (NCHUNK, HEADS, BATCH), 256 threads; each thread owns 4 Gram entries.
__global__ void attn_partial(const float* __restrict__ qkv) {
    const int b = blockIdx.z, h = blockIdx.y, chunk = blockIdx.x;
    const float* q = qkv + ((size_t)b * 384 + h * 32) * NSP;
    const float* k = qkv + ((size_t)b * 384 + 128 + h * 32) * NSP;

    __shared__ float qs[32][TS + 1];
    __shared__ float ks[32][TS + 1];

    const int tid = threadIdx.x;
    const int e0 = tid * 4;
    const int ci = e0 >> 5;
    const int cj0 = e0 & 31;

    float acc[4] = {};
    float qn = 0.f, kn = 0.f;
    const int sbase0 = chunk * CHUNK;

    for (int t = 0; t < CHUNK / TS; t++) {
        int sbase = sbase0 + t * TS;
        for (int l = tid; l < 32 * TS; l += 256) {
            int c = l / TS, ss = l % TS;
            qs[c][ss] = q[(size_t)c * NSP + sbase + ss];
            ks[c][ss] = k[(size_t)c * NSP + sbase + ss];
        }
        __syncthreads();
        #pragma unroll 4
        for (int ss = 0; ss < TS; ss++) {
            float qv = qs[ci][ss];
            acc[0] += qv * ks[cj0 + 0][ss];
            acc[1] += qv * ks[cj0 + 1][ss];
            acc[2] += qv * ks[cj0 + 2][ss];
            acc[3] += qv * ks[cj0 + 3][ss];
        }
        if (tid < 32) {
            for (int ss = 0; ss < TS; ss++) {
                float a = qs[tid][ss]; qn += a * a;
                float c2 = ks[tid][ss]; kn += c2 * c2;
            }
        }
        __syncthreads();
    }

    int bh = b * HEADS + h;
    float* Gp = g_Gp + ((size_t)chunk * BATCH * HEADS + bh) * 1024;
    Gp[e0 + 0] = acc[0]; Gp[e0 + 1] = acc[1];
    Gp[e0 + 2] = acc[2]; Gp[e0 + 3] = acc[3];
    if (tid < 32) {
        g_qnp[((size_t)chunk * BATCH * HEADS + bh) * 32 + tid] = qn;
        g_knp[((size_t)chunk * BATCH * HEADS + bh) * 32 + tid] = kn;
    }
}

// ---------------- attention stage 2: reduce, normalize, softmax ----------------
// grid (HEADS, BATCH), 32 threads (one per ci)
__global__ void attn_finalize(const float* __restrict__ temperature) {
    const int b = blockIdx.y, h = blockIdx.x;
    const int bh = b * HEADS + h;
    const int ci = threadIdx.x;

    __shared__ float qn_s[32], kn_s[32];
    float qn = 0.f, kn = 0.f;
    for (int c = 0; c < NCHUNK; c++) {
        qn += g_qnp[((size_t)c * BATCH * HEADS + bh) * 32 + ci];
        kn += g_knp[((size_t)c * BATCH * HEADS + bh) * 32 + ci];
    }
    qn_s[ci] = fmaxf(sqrtf(qn), 1e-12f);
    kn_s[ci] = fmaxf(sqrtf(kn), 1e-12f);
    __syncwarp();

    float T = temperature[h];
    float qi = qn_s[ci];
    float lg[32];
    float mx = -1e30f;
    #pragma unroll
    for (int cj = 0; cj < 32; cj++) {
        float g = 0.f;
        for (int c = 0; c < NCHUNK; c++)
            g += g_Gp[(((size_t)c * BATCH * HEADS + bh) * 1024) + ci * 32 + cj];
        float v = g / (qi * kn_s[cj]) * T;
        lg[cj] = v;
        mx = fmaxf(mx, v);
    }
    float s = 0.f;
    #pragma unroll
    for (int cj = 0; cj < 32; cj++) { lg[cj] = __expf(lg[cj] - mx); s += lg[cj]; }
    float inv = 1.f / s;
    float* A = g_attn + (size_t)bh * 1024;
    #pragma unroll
    for (int cj = 0; cj < 32; cj++) A[ci * 32 + cj] = lg[cj] * inv;
}

// ---------------- attention stage 3: out = attn @ v -> g_buf1 [B,128,NSP] ------
// grid (NSP/256, HEADS, BATCH), 256 threads; one s per thread, 32 channels out.
__global__ void attn_apply(const float* __restrict__ qkv, float* __restrict__ out) {
    const int b = blockIdx.z, h = blockIdx.y;
    const int s = blockIdx.x * 256 + threadIdx.x;
    __shared__ float A[1024];
    for (int l = threadIdx.x; l < 1024; l += 256)
        A[l] = g_attn[((size_t)(b * HEADS + h)) * 1024 + l];
    __syncthreads();

    const float* v = qkv + ((size_t)b * 384 + 256 + h * 32) * NSP;
    float acc[32] = {};
    #pragma unroll 4
    for (int cj = 0; cj < 32; cj++) {
        float vv = v[(size_t)cj * NSP + s];
        #pragma unroll
        for (int ci = 0; ci < 32; ci++) acc[ci] += A[ci * 32 + cj] * vv;
    }
    float* ob = out + ((size_t)b * 128 + h * 32) * NSP;
    #pragma unroll
    for (int ci = 0; ci < 32; ci++) ob[(size_t)ci * NSP + s] = acc[ci];
}

// ---------------- launch ----------------
extern "C" void kernel_launch(void* const* d_in, const int* in_sizes, int n_in,
                              void* d_out, int out_size) {
    const float* x      = (const float*)d_in[0];
    const float* qkv_r  = (const float*)d_in[1];
    const float* qkv_i  = (const float*)d_in[2];
    const float* qkv_j  = (const float*)d_in[3];
    const float* qkv_k  = (const float*)d_in[4];
    const float* qkv_b  = (const float*)d_in[5];
    const float* dw_r   = (const float*)d_in[6];
    const float* dw_i   = (const float*)d_in[7];
    const float* dw_j   = (const float*)d_in[8];
    const float* dw_k   = (const float*)d_in[9];
    const float* dw_b   = (const float*)d_in[10];
    const float* po_r   = (const float*)d_in[11];
    const float* po_i   = (const float*)d_in[12];
    const float* po_j   = (const float*)d_in[13];
    const float* po_k   = (const float*)d_in[14];
    const float* po_b   = (const float*)d_in[15];
    const float* temp   = (const float*)d_in[16];
    float* out = (float*)d_out;

    float *w_qkv, *w_dw, *w_po, *buf1, *buf2;
    cudaGetSymbolAddress((void**)&w_qkv, g_w_qkv);
    cudaGetSymbolAddress((void**)&w_dw,  g_w_dw);
    cudaGetSymbolAddress((void**)&w_po,  g_w_po);
    cudaGetSymbolAddress((void**)&buf1,  g_buf1);
    cudaGetSymbolAddress((void**)&buf2,  g_buf2);

    // 1) materialize quaternion weights
    build_weight<<<192, 256>>>(qkv_r, qkv_i, qkv_j, qkv_k, w_qkv, 96, 32, 1);
    build_weight<<<5184, 256>>>(dw_r, dw_i, dw_j, dw_k, w_dw, 96, 96, 9);
    build_weight<<<64, 256>>>(po_r, po_i, po_j, po_k, w_po, 32, 32, 1);

    // 2) qkv 1x1 conv: [B,128,NSP] -> [B,384,NSP]
    conv_gemm<1, 0><<<dim3(NSP / 64, 384 / 64, BATCH), 256>>>(w_qkv, x, qkv_b, buf1, 384, 128);

    // 3) dw 3x3 conv: [B,384,NSP] -> [B,384,NSP]   (the big one)
    conv_gemm<3, 1><<<dim3(NSP / 64, 384 / 64, BATCH), 256>>>(w_dw, buf1, dw_b, buf2, 384, 384);

    // 4) channel attention
    attn_partial<<<dim3(NCHUNK, HEADS, BATCH), 256>>>(buf2);
    attn_finalize<<<dim3(HEADS, BATCH), 32>>>(temp);
    attn_apply<<<dim3(NSP / 256, HEADS, BATCH), 256>>>(buf2, buf1);

    // 5) po 1x1 conv: [B,128,NSP] -> d_out
    conv_gemm<1, 0><<<dim3(NSP / 64, 128 / 64, BATCH), 256>>>(w_po, buf1, po_b, out, 128, 128);
}

// round 7
// speedup vs baseline: 1.2477x; 1.2477x over previous
#include <cuda_runtime.h>
#include <math.h>

#define HWDIM 128
#define NSP   16384   // 128*128
#define BATCH 2
#define HEADS 4
#define NCHUNK 16     // s-chunks for attention partial reduction
#define CHUNK  1024   // NSP / NCHUNK
#define TS     128    // smem tile of s per inner iteration

// ---------------- scratch (static device memory; no allocations) ----------------
__device__ float g_w_qkv[384 * 128];          // full quaternion 1x1 qkv weight
__device__ float g_w_dw [384 * 384 * 9];      // full quaternion 3x3 dw weight
__device__ float g_w_po [128 * 128];          // full quaternion 1x1 po weight
__device__ float g_buf1[(size_t)BATCH * 384 * NSP];  // qkv1 out, later attn out (as [B,128,NSP])
__device__ float g_buf2[(size_t)BATCH * 384 * NSP];  // dw out (q|k|v)
__device__ float g_Gp [NCHUNK * BATCH * HEADS * 32 * 32]; // partial Gram
__device__ float g_qnp[NCHUNK * BATCH * HEADS * 32];      // partial sum q^2
__device__ float g_knp[NCHUNK * BATCH * HEADS * 32];      // partial sum k^2
__device__ float g_attn[BATCH * HEADS * 32 * 32];         // softmaxed attention

// Hamilton product block table: W[p-block][q-block] = sign * component
__constant__ int   c_cidx[16] = {0,1,2,3, 1,0,3,2, 2,3,0,1, 3,2,1,0};
__constant__ float c_sign[16] = {1,-1,-1,-1, 1,1,-1,1, 1,1,1,-1, 1,-1,1,1};

// ---------------- build full quaternion weight ----------------
__global__ void build_weight(const float* __restrict__ r, const float* __restrict__ i,
                             const float* __restrict__ j, const float* __restrict__ k,
                             float* __restrict__ W, int Po, int Pi, int KHW) {
    const float* comps[4] = {r, i, j, k};
    int total = 4 * Po * 4 * Pi * KHW;
    for (int idx = blockIdx.x * blockDim.x + threadIdx.x; idx < total;
         idx += gridDim.x * blockDim.x) {
        int o   = idx / (4 * Pi * KHW);
        int rem = idx % (4 * Pi * KHW);
        int c   = rem / KHW;
        int kk  = rem % KHW;
        int p = o / Po, q = c / Pi;
        int t = p * 4 + q;
        const float* src = comps[c_cidx[t]];
        W[idx] = c_sign[t] * src[((o % Po) * Pi + (c % Pi)) * KHW + kk];
    }
}

// ---------------- implicit-GEMM conv (KS=1 or 3, pad=PAD), NCHW ----------------
// C[m,n] = sum_k W[m,k] * im2col(in)[k,n] + bias[m]
// Tile: 128(m) x 128(n) x 8(k); 256 threads; 8x8 micro-tile in 4+64 split layout.
// Register prefetch of the next k-slab overlaps gmem latency with FFMA.
template <int KS, int PAD>
__global__ void __launch_bounds__(256, 2)
conv_gemm(const float* __restrict__ W, const float* __restrict__ in,
          const float* __restrict__ bias, float* __restrict__ out,
          int Cout, int Cin) {
    const int K = Cin * KS * KS;
    const int b = blockIdx.z;
    const int m0 = blockIdx.y * 128, n0 = blockIdx.x * 128;
    const float* inb = in + (size_t)b * Cin * NSP;

    __shared__ float As[8][128];
    __shared__ float Bs[8][128];

    const int tid = threadIdx.x;
    const int tx = tid & 15, ty = tid >> 4;
    // A loader: 2 threads per m-row, float4 along K
    const int ma = tid >> 1, ka = (tid & 1) * 4;
    // B loader: one k-row per 32 threads, float4 along n
    const int kb = tid >> 5, n4 = (tid & 31) * 4;

    float4 aReg;
    float  bReg[4];

    // gmem -> regs for k-slab starting at k0
    auto load_slab = [&](int k0) {
        aReg = *(const float4*)&W[(size_t)(m0 + ma) * K + k0 + ka];
        if (KS == 1) {
            float4 bv = *(const float4*)&inb[(size_t)(k0 + kb) * NSP + n0 + n4];
            bReg[0] = bv.x; bReg[1] = bv.y; bReg[2] = bv.z; bReg[3] = bv.w;
        } else {
            int kk = k0 + kb;
            int cch = kk / 9;
            int rem = kk - cch * 9;
            int ky = rem / 3, kx = rem - ky * 3;
            int y = (n0 + n4) >> 7;            // whole tile sits in one image row
            int iy = y + ky - PAD;
            bool yok = (iy >= 0 && iy < HWDIM);
            const float* rowp = inb + ((size_t)cch * HWDIM + iy) * HWDIM;
            #pragma unroll
            for (int i2 = 0; i2 < 4; i2++) {
                int x = (n4 + i2) & 127;       // n0 is a multiple of 128
                int ix = x + kx - PAD;
                bReg[i2] = (yok && ix >= 0 && ix < HWDIM) ? rowp[ix] : 0.f;
            }
        }
    };

    float acc[8][8] = {};

    load_slab(0);
    for (int k0 = 0; k0 < K; k0 += 8) {
        // regs -> smem (previous compute finished at loop-bottom sync)
        As[ka + 0][ma] = aReg.x; As[ka + 1][ma] = aReg.y;
        As[ka + 2][ma] = aReg.z; As[ka + 3][ma] = aReg.w;
        Bs[kb][n4 + 0] = bReg[0]; Bs[kb][n4 + 1] = bReg[1];
        Bs[kb][n4 + 2] = bReg[2]; Bs[kb][n4 + 3] = bReg[3];
        __syncthreads();

        if (k0 + 8 < K) load_slab(k0 + 8);   // prefetch next slab into regs

        #pragma unroll
        for (int kk = 0; kk < 8; kk++) {
            float4 a0 = *(const float4*)&As[kk][ty * 4];
            float4 a1 = *(const float4*)&As[kk][ty * 4 + 64];
            float4 b0 = *(const float4*)&Bs[kk][tx * 4];
            float4 b1 = *(const float4*)&Bs[kk][tx * 4 + 64];
            float av[8] = {a0.x, a0.y, a0.z, a0.w, a1.x, a1.y, a1.z, a1.w};
            float bv[8] = {b0.x, b0.y, b0.z, b0.w, b1.x, b1.y, b1.z, b1.w};
            #pragma unroll
            for (int im = 0; im < 8; im++)
                #pragma unroll
                for (int jn = 0; jn < 8; jn++)
                    acc[im][jn] += av[im] * bv[jn];
        }
        __syncthreads();
    }

    float* outb = out + (size_t)b * Cout * NSP;
    #pragma unroll
    for (int im = 0; im < 8; im++) {
        int m = m0 + ((im < 4) ? (ty * 4 + im) : (64 + ty * 4 + im - 4));
        float bs = bias[m];
        float4 o0 = make_float4(acc[im][0] + bs, acc[im][1] + bs,
                                acc[im][2] + bs, acc[im][3] + bs);
        float4 o1 = make_float4(acc[im][4] + bs, acc[im][5] + bs,
                                acc[im][6] + bs, acc[im][7] + bs);
        *(float4*)&outb[(size_t)m * NSP + n0 + tx * 4]      = o0;
        *(float4*)&outb[(size_t)m * NSP + n0 + tx * 4 + 64] = o1;
    }
}

// ---------------- attention stage 1: partial Gram + norms (deterministic) ------
// grid (NCHUNK, HEADS, BATCH), 256 threads; each thread owns 4 Gram entries.
__global__ void attn_partial(const float* __restrict__ qkv) {
    const int b = blockIdx.z, h = blockIdx.y, chunk = blockIdx.x;
    const float* q = qkv + ((size_t)b * 384 + h * 32) * NSP;
    const float* k = qkv + ((size_t)b * 384 + 128 + h * 32) * NSP;

    __shared__ float qs[32][TS + 1];
    __shared__ float ks[32][TS + 1];

    const int tid = threadIdx.x;
    const int e0 = tid * 4;
    const int ci = e0 >> 5;
    const int cj0 = e0 & 31;

    float acc[4] = {};
    float qn = 0.f, kn = 0.f;
    const int sbase0 = chunk * CHUNK;

    for (int t = 0; t < CHUNK / TS; t++) {
        int sbase = sbase0 + t * TS;
        for (int l = tid; l < 32 * TS; l += 256) {
            int c = l / TS, ss = l % TS;
            qs[c][ss] = q[(size_t)c * NSP + sbase + ss];
            ks[c][ss] = k[(size_t)c * NSP + sbase + ss];
        }
        __syncthreads();
        #pragma unroll 4
        for (int ss = 0; ss < TS; ss++) {
            float qv = qs[ci][ss];
            acc[0] += qv * ks[cj0 + 0][ss];
            acc[1] += qv * ks[cj0 + 1][ss];
            acc[2] += qv * ks[cj0 + 2][ss];
            acc[3] += qv * ks[cj0 + 3][ss];
        }
        if (tid < 32) {
            for (int ss = 0; ss < TS; ss++) {
                float a = qs[tid][ss]; qn += a * a;
                float c2 = ks[tid][ss]; kn += c2 * c2;
            }
        }
        __syncthreads();
    }

    int bh = b * HEADS + h;
    float* Gp = g_Gp + ((size_t)chunk * BATCH * HEADS + bh) * 1024;
    Gp[e0 + 0] = acc[0]; Gp[e0 + 1] = acc[1];
    Gp[e0 + 2] = acc[2]; Gp[e0 + 3] = acc[3];
    if (tid < 32) {
        g_qnp[((size_t)chunk * BATCH * HEADS + bh) * 32 + tid] = qn;
        g_knp[((size_t)chunk * BATCH * HEADS + bh) * 32 + tid] = kn;
    }
}

// ---------------- attention stage 2: reduce, normalize, softmax ----------------
// grid (HEADS, BATCH), 32 threads (one per ci)
__global__ void attn_finalize(const float* __restrict__ temperature) {
    const int b = blockIdx.y, h = blockIdx.x;
    const int bh = b * HEADS + h;
    const int ci = threadIdx.x;

    __shared__ float qn_s[32], kn_s[32];
    float qn = 0.f, kn = 0.f;
    for (int c = 0; c < NCHUNK; c++) {
        qn += g_qnp[((size_t)c * BATCH * HEADS + bh) * 32 + ci];
        kn += g_knp[((size_t)c * BATCH * HEADS + bh) * 32 + ci];
    }
    qn_s[ci] = fmaxf(sqrtf(qn), 1e-12f);
    kn_s[ci] = fmaxf(sqrtf(kn), 1e-12f);
    __syncwarp();

    float T = temperature[h];
    float qi = qn_s[ci];
    float lg[32];
    float mx = -1e30f;
    #pragma unroll
    for (int cj = 0; cj < 32; cj++) {
        float g = 0.f;
        for (int c = 0; c < NCHUNK; c++)
            g += g_Gp[(((size_t)c * BATCH * HEADS + bh) * 1024) + ci * 32 + cj];
        float v = g / (qi * kn_s[cj]) * T;
        lg[cj] = v;
        mx = fmaxf(mx, v);
    }
    float s = 0.f;
    #pragma unroll
    for (int cj = 0; cj < 32; cj++) { lg[cj] = __expf(lg[cj] - mx); s += lg[cj]; }
    float inv = 1.f / s;
    float* A = g_attn + (size_t)bh * 1024;
    #pragma unroll
    for (int cj = 0; cj < 32; cj++) A[ci * 32 + cj] = lg[cj] * inv;
}

// ---------------- attention stage 3: out = attn @ v -> g_buf1 [B,128,NSP] ------
// grid (NSP/256, HEADS, BATCH), 256 threads; one s per thread, 32 channels out.
__global__ void attn_apply(const float* __restrict__ qkv, float* __restrict__ out) {
    const int b = blockIdx.z, h = blockIdx.y;
    const int s = blockIdx.x * 256 + threadIdx.x;
    __shared__ float A[1024];
    for (int l = threadIdx.x; l < 1024; l += 256)
        A[l] = g_attn[((size_t)(b * HEADS + h)) * 1024 + l];
    __syncthreads();

    const float* v = qkv + ((size_t)b * 384 + 256 + h * 32) * NSP;
    float acc[32] = {};
    #pragma unroll 4
    for (int cj = 0; cj < 32; cj++) {
        float vv = v[(size_t)cj * NSP + s];
        #pragma unroll
        for (int ci = 0; ci < 32; ci++) acc[ci] += A[ci * 32 + cj] * vv;
    }
    float* ob = out + ((size_t)b * 128 + h * 32) * NSP;
    #pragma unroll
    for (int ci = 0; ci < 32; ci++) ob[(size_t)ci * NSP + s] = acc[ci];
}

// ---------------- launch ----------------
extern "C" void kernel_launch(void* const* d_in, const int* in_sizes, int n_in,
                              void* d_out, int out_size) {
    const float* x      = (const float*)d_in[0];
    const float* qkv_r  = (const float*)d_in[1];
    const float* qkv_i  = (const float*)d_in[2];
    const float* qkv_j  = (const float*)d_in[3];
    const float* qkv_k  = (const float*)d_in[4];
    const float* qkv_b  = (const float*)d_in[5];
    const float* dw_r   = (const float*)d_in[6];
    const float* dw_i   = (const float*)d_in[7];
    const float* dw_j   = (const float*)d_in[8];
    const float* dw_k   = (const float*)d_in[9];
    const float* dw_b   = (const float*)d_in[10];
    const float* po_r   = (const float*)d_in[11];
    const float* po_i   = (const float*)d_in[12];
    const float* po_j   = (const float*)d_in[13];
    const float* po_k   = (const float*)d_in[14];
    const float* po_b   = (const float*)d_in[15];
    const float* temp   = (const float*)d_in[16];
    float* out = (float*)d_out;

    float *w_qkv, *w_dw, *w_po, *buf1, *buf2;
    cudaGetSymbolAddress((void**)&w_qkv, g_w_qkv);
    cudaGetSymbolAddress((void**)&w_dw,  g_w_dw);
    cudaGetSymbolAddress((void**)&w_po,  g_w_po);
    cudaGetSymbolAddress((void**)&buf1,  g_buf1);
    cudaGetSymbolAddress((void**)&buf2,  g_buf2);

    // 1) materialize quaternion weights
    build_weight<<<192, 256>>>(qkv_r, qkv_i, qkv_j, qkv_k, w_qkv, 96, 32, 1);
    build_weight<<<5184, 256>>>(dw_r, dw_i, dw_j, dw_k, w_dw, 96, 96, 9);
    build_weight<<<64, 256>>>(po_r, po_i, po_j, po_k, w_po, 32, 32, 1);

    // 2) qkv 1x1 conv: [B,128,NSP] -> [B,384,NSP]
    conv_gemm<1, 0><<<dim3(NSP / 128, 384 / 128, BATCH), 256>>>(w_qkv, x, qkv_b, buf1, 384, 128);

    // 3) dw 3x3 conv: [B,384,NSP] -> [B,384,NSP]   (the big one)
    conv_gemm<3, 1><<<dim3(NSP / 128, 384 / 128, BATCH), 256>>>(w_dw, buf1, dw_b, buf2, 384, 384);

    // 4) channel attention
    attn_partial<<<dim3(NCHUNK, HEADS, BATCH), 256>>>(buf2);
    attn_finalize<<<dim3(HEADS, BATCH), 32>>>(temp);
    attn_apply<<<dim3(NSP / 256, HEADS, BATCH), 256>>>(buf2, buf1);

    // 5) po 1x1 conv: [B,128,NSP] -> d_out
    conv_gemm<1, 0><<<dim3(NSP / 128, 128 / 128, BATCH), 256>>>(w_po, buf1, po_b, out, 128, 128);
}

// round 12
// speedup vs baseline: 2.0994x; 1.6826x over previous
#include <cuda_runtime.h>
#include <cuda_bf16.h>
#include <math.h>
#include <stdint.h>

#define HWDIM 128
#define NSP   16384   // 128*128
#define BATCH 2
#define HEADS 4
#define NCHUNK 16
#define CHUNK  1024
#define TS     128

// ---------------- scratch (static device memory; no allocations) ----------------
__device__ float g_w_qkv[384 * 128];
__device__ float g_w_dw [384 * 3456];
__device__ float g_w_po [128 * 128];
__device__ float g_buf1[(size_t)BATCH * 384 * NSP];
__device__ float g_buf2[(size_t)BATCH * 384 * NSP];
__device__ float g_Gp [NCHUNK * BATCH * HEADS * 32 * 32];
__device__ float g_qnp[NCHUNK * BATCH * HEADS * 32];
__device__ float g_knp[NCHUNK * BATCH * HEADS * 32];
__device__ float g_attn[BATCH * HEADS * 32 * 32];

__constant__ int   c_cidx[16] = {0,1,2,3, 1,0,3,2, 2,3,0,1, 3,2,1,0};
__constant__ float c_sign[16] = {1,-1,-1,-1, 1,1,-1,1, 1,1,1,-1, 1,-1,1,1};

// ---------------- build full quaternion weight (fp32) ----------------
__global__ void build_weight(const float* __restrict__ r, const float* __restrict__ i,
                             const float* __restrict__ j, const float* __restrict__ k,
                             float* __restrict__ W, int Po, int Pi, int KHW) {
    const float* comps[4] = {r, i, j, k};
    int total = 4 * Po * 4 * Pi * KHW;
    for (int idx = blockIdx.x * blockDim.x + threadIdx.x; idx < total;
         idx += gridDim.x * blockDim.x) {
        int o   = idx / (4 * Pi * KHW);
        int rem = idx % (4 * Pi * KHW);
        int c   = rem / KHW;
        int kk  = rem % KHW;
        int t = (o / Po) * 4 + (c / Pi);
        W[idx] = c_sign[t] * comps[c_cidx[t]][((o % Po) * Pi + (c % Pi)) * KHW + kk];
    }
}

// ---------------- bf16 m16n8k16 mma.sync helper ----------------
__device__ __forceinline__ void mma_bf16(float* c, const uint32_t* a, const uint32_t* b) {
    asm volatile(
        "mma.sync.aligned.m16n8k16.row.col.f32.bf16.bf16.f32 "
        "{%0,%1,%2,%3}, {%4,%5,%6,%7}, {%8,%9}, {%0,%1,%2,%3};"
        : "+f"(c[0]), "+f"(c[1]), "+f"(c[2]), "+f"(c[3])
        : "r"(a[0]), "r"(a[1]), "r"(a[2]), "r"(a[3]), "r"(b[0]), "r"(b[1]));
}

// pack two floats into bf16x2 word (lo half = first/lower-k element)
__device__ __forceinline__ uint32_t packbf(float a, float b) {
    __nv_bfloat162 t = __floats2bfloat162_rn(a, b);
    return *reinterpret_cast<uint32_t*>(&t);
}
__device__ __forceinline__ float bfres(float f) {   // residual after bf16 rounding
    return f - __bfloat162float(__float2bfloat16_rn(f));
}

// ---------------- bf16x3-split implicit-GEMM conv (KS=1 or 3), NCHW ----------------
// C[m,n] = sum_k W[m,k] * im2col(X)[k,n] + bias[m], fp32-accurate via hi/lo split:
//   acc = Whi*Xhi + Whi*Xlo + Wlo*Xhi   (fp32 accumulators)
// CTA 128x128x32, 8 warps (2m x 4n), warp tile 64x32, m16n8k16 bf16 MMA.
// Single smem stage + register prefetch double buffering.
#define A_STW 20    // words per A row: 16 (32 k as bf16x2) + 4 pad
#define B_STW 136   // words per B kw-row: 128 n + 8 pad

template <int KS, int PAD>
__global__ void __launch_bounds__(256, 1)
conv_mma(const float* __restrict__ W, const float* __restrict__ in,
         const float* __restrict__ bias, float* __restrict__ out,
         int Cout, int Cin) {
    __shared__ uint32_t AsH[128 * A_STW];
    __shared__ uint32_t AsL[128 * A_STW];
    __shared__ uint32_t BsH[16 * B_STW];
    __shared__ uint32_t BsL[16 * B_STW];

    const int K  = Cin * KS * KS;
    const int NC = K / 32;
    const int b  = blockIdx.z;
    const int m0 = blockIdx.y * 128, n0 = blockIdx.x * 128;
    const float* inb = in + (size_t)b * Cin * NSP;

    const int tid  = threadIdx.x;
    const int w    = tid >> 5, lane = tid & 31;
    const int gid  = lane >> 2, tig = lane & 3;
    const int mw   = (w >> 2) * 64;   // warp m offset (0/64)
    const int nw   = (w & 3) * 32;    // warp n offset

    float4 pa[4];         // A prefetch: 4 x float4 (16 fp32)
    float  pb[2][2][4];   // B prefetch: 2 its x {k even,k odd} x 4 n (16 fp32)

    auto load_chunk = [&](int k0) {
        #pragma unroll
        for (int it = 0; it < 4; it++) {
            int idx = it * 256 + tid;
            int am = idx >> 3, ak = (idx & 7) * 4;
            pa[it] = *(const float4*)&W[(size_t)(m0 + am) * K + k0 + ak];
        }
        #pragma unroll
        for (int it = 0; it < 2; it++) {
            int idx = it * 256 + tid;
            int kw = idx >> 5, nf = idx & 31;
            int n4 = nf * 4;
            #pragma unroll
            for (int kp = 0; kp < 2; kp++) {
                int kk = k0 + kw * 2 + kp;
                if (KS == 1) {
                    float4 xv = *(const float4*)&inb[(size_t)kk * NSP + n0 + n4];
                    pb[it][kp][0] = xv.x; pb[it][kp][1] = xv.y;
                    pb[it][kp][2] = xv.z; pb[it][kp][3] = xv.w;
                } else {
                    int cch = kk / 9;
                    int rem = kk - cch * 9;
                    int ky = rem / 3, kx = rem - ky * 3;
                    int n = n0 + n4;
                    int y = n >> 7, x = n & 127;
                    int iy = y + ky - PAD;
                    bool yok = (unsigned)iy < (unsigned)HWDIM;
                    const float* rowp = inb + ((size_t)cch << 14) + ((size_t)iy << 7);
                    int ix0 = x + kx - PAD;
                    #pragma unroll
                    for (int i2 = 0; i2 < 4; i2++)
                        pb[it][kp][i2] = (yok && (unsigned)(ix0 + i2) < 128u)
                                             ? __ldg(rowp + ix0 + i2) : 0.f;
                }
            }
        }
    };

    float acc[4][4][4] = {};

    load_chunk(0);
    for (int c = 0; c < NC; c++) {
        // regs -> smem, split into bf16 hi/lo
        #pragma unroll
        for (int it = 0; it < 4; it++) {
            int idx = it * 256 + tid;
            int am = idx >> 3, aw = (idx & 7) * 2;   // word offset within row
            float f0 = pa[it].x, f1 = pa[it].y, f2 = pa[it].z, f3 = pa[it].w;
            uint2 hw = make_uint2(packbf(f0, f1), packbf(f2, f3));
            uint2 lw = make_uint2(packbf(bfres(f0), bfres(f1)),
                                  packbf(bfres(f2), bfres(f3)));
            *(uint2*)&AsH[am * A_STW + aw] = hw;
            *(uint2*)&AsL[am * A_STW + aw] = lw;
        }
        #pragma unroll
        for (int it = 0; it < 2; it++) {
            int idx = it * 256 + tid;
            int kw = idx >> 5, nf = idx & 31;
            int n4 = nf * 4;
            uint4 hw, lw;
            hw.x = packbf(pb[it][0][0], pb[it][1][0]);
            hw.y = packbf(pb[it][0][1], pb[it][1][1]);
            hw.z = packbf(pb[it][0][2], pb[it][1][2]);
            hw.w = packbf(pb[it][0][3], pb[it][1][3]);
            lw.x = packbf(bfres(pb[it][0][0]), bfres(pb[it][1][0]));
            lw.y = packbf(bfres(pb[it][0][1]), bfres(pb[it][1][1]));
            lw.z = packbf(bfres(pb[it][0][2]), bfres(pb[it][1][2]));
            lw.w = packbf(bfres(pb[it][0][3]), bfres(pb[it][1][3]));
            *(uint4*)&BsH[kw * B_STW + n4] = hw;
            *(uint4*)&BsL[kw * B_STW + n4] = lw;
        }
        __syncthreads();

        if (c + 1 < NC) load_chunk((c + 1) * 32);   // prefetch next chunk

        #pragma unroll
        for (int ks = 0; ks < 2; ks++) {
            const int kw0 = ks * 8;                 // word base of this k16 block
            uint32_t ah[4][4], al[4][4], bh[4][2], bl[4][2];
            #pragma unroll
            for (int mt = 0; mt < 4; mt++) {
                int r0 = (mw + mt * 16 + gid) * A_STW;
                int r8 = r0 + 8 * A_STW;
                ah[mt][0] = AsH[r0 + kw0 + tig];
                ah[mt][1] = AsH[r8 + kw0 + tig];
                ah[mt][2] = AsH[r0 + kw0 + tig + 4];
                ah[mt][3] = AsH[r8 + kw0 + tig + 4];
                al[mt][0] = AsL[r0 + kw0 + tig];
                al[mt][1] = AsL[r8 + kw0 + tig];
                al[mt][2] = AsL[r0 + kw0 + tig + 4];
                al[mt][3] = AsL[r8 + kw0 + tig + 4];
            }
            #pragma unroll
            for (int nt = 0; nt < 4; nt++) {
                int nc0 = nw + nt * 8 + gid;
                bh[nt][0] = BsH[(kw0 + tig) * B_STW + nc0];
                bh[nt][1] = BsH[(kw0 + tig + 4) * B_STW + nc0];
                bl[nt][0] = BsL[(kw0 + tig) * B_STW + nc0];
                bl[nt][1] = BsL[(kw0 + tig + 4) * B_STW + nc0];
            }
            #pragma unroll
            for (int mt = 0; mt < 4; mt++)
                #pragma unroll
                for (int nt = 0; nt < 4; nt++) {
                    mma_bf16(acc[mt][nt], ah[mt], bh[nt]);
                    mma_bf16(acc[mt][nt], ah[mt], bl[nt]);
                    mma_bf16(acc[mt][nt], al[mt], bh[nt]);
                }
        }
        __syncthreads();
    }

    // epilogue: direct fragment stores (+bias), float2 per row-half
    float* outb = out + (size_t)b * Cout * NSP;
    #pragma unroll
    for (int mt = 0; mt < 4; mt++) {
        int m = m0 + mw + mt * 16 + gid;
        float bs0 = bias[m], bs1 = bias[m + 8];
        #pragma unroll
        for (int nt = 0; nt < 4; nt++) {
            int n = n0 + nw + nt * 8 + tig * 2;
            float2 v0 = make_float2(acc[mt][nt][0] + bs0, acc[mt][nt][1] + bs0);
            float2 v1 = make_float2(acc[mt][nt][2] + bs1, acc[mt][nt][3] + bs1);
            *(float2*)&outb[(size_t)m * NSP + n]       = v0;
            *(float2*)&outb[(size_t)(m + 8) * NSP + n] = v1;
        }
    }
}

// ---------------- attention stage 1: partial Gram + norms (deterministic) ------
__global__ void attn_partial(const float* __restrict__ qkv) {
    const int b = blockIdx.z, h = blockIdx.y, chunk = blockIdx.x;
    const float* q = qkv + ((size_t)b * 384 + h * 32) * NSP;
    const float* k = qkv + ((size_t)b * 384 + 128 + h * 32) * NSP;

    __shared__ float qs[32][TS + 1];
    __shared__ float ks[32][TS + 1];

    const int tid = threadIdx.x;
    const int e0 = tid * 4;
    const int ci = e0 >> 5;
    const int cj0 = e0 & 31;

    float acc[4] = {};
    float qn = 0.f, kn = 0.f;
    const int sbase0 = chunk * CHUNK;

    for (int t = 0; t < CHUNK / TS; t++) {
        int sbase = sbase0 + t * TS;
        for (int l = tid; l < 32 * TS; l += 256) {
            int c = l / TS, ss = l % TS;
            qs[c][ss] = q[(size_t)c * NSP + sbase + ss];
            ks[c][ss] = k[(size_t)c * NSP + sbase + ss];
        }
        __syncthreads();
        #pragma unroll 4
        for (int ss = 0; ss < TS; ss++) {
            float qv = qs[ci][ss];
            acc[0] += qv * ks[cj0 + 0][ss];
            acc[1] += qv * ks[cj0 + 1][ss];
            acc[2] += qv * ks[cj0 + 2][ss];
            acc[3] += qv * ks[cj0 + 3][ss];
        }
        if (tid < 32) {
            for (int ss = 0; ss < TS; ss++) {
                float a = qs[tid][ss]; qn += a * a;
                float c2 = ks[tid][ss]; kn += c2 * c2;
            }
        }
        __syncthreads();
    }

    int bh = b * HEADS + h;
    float* Gp = g_Gp + ((size_t)chunk * BATCH * HEADS + bh) * 1024;
    Gp[e0 + 0] = acc[0]; Gp[e0 + 1] = acc[1];
    Gp[e0 + 2] = acc[2]; Gp[e0 + 3] = acc[3];
    if (tid < 32) {
        g_qnp[((size_t)chunk * BATCH * HEADS + bh) * 32 + tid] = qn;
        g_knp[((size_t)chunk * BATCH * HEADS + bh) * 32 + tid] = kn;
    }
}

// ---------------- attention stage 2: reduce, normalize, softmax ----------------
__global__ void attn_finalize(const float* __restrict__ temperature) {
    const int b = blockIdx.y, h = blockIdx.x;
    const int bh = b * HEADS + h;
    const int ci = threadIdx.x;

    __shared__ float qn_s[32], kn_s[32];
    float qn = 0.f, kn = 0.f;
    for (int c = 0; c < NCHUNK; c++) {
        qn += g_qnp[((size_t)c * BATCH * HEADS + bh) * 32 + ci];
        kn += g_knp[((size_t)c * BATCH * HEADS + bh) * 32 + ci];
    }
    qn_s[ci] = fmaxf(sqrtf(qn), 1e-12f);
    kn_s[ci] = fmaxf(sqrtf(kn), 1e-12f);
    __syncwarp();

    float T = temperature[h];
    float qi = qn_s[ci];
    float lg[32];
    float mx = -1e30f;
    #pragma unroll
    for (int cj = 0; cj < 32; cj++) {
        float g = 0.f;
        for (int c = 0; c < NCHUNK; c++)
            g += g_Gp[(((size_t)c * BATCH * HEADS + bh) * 1024) + ci * 32 + cj];
        float v = g / (qi * kn_s[cj]) * T;
        lg[cj] = v;
        mx = fmaxf(mx, v);
    }
    float s = 0.f;
    #pragma unroll
    for (int cj = 0; cj < 32; cj++) { lg[cj] = __expf(lg[cj] - mx); s += lg[cj]; }
    float inv = 1.f / s;
    float* A = g_attn + (size_t)bh * 1024;
    #pragma unroll
    for (int cj = 0; cj < 32; cj++) A[ci * 32 + cj] = lg[cj] * inv;
}

// ---------------- attention stage 3: out = attn @ v ----------------
__global__ void attn_apply(const float* __restrict__ qkv, float* __restrict__ out) {
    const int b = blockIdx.z, h = blockIdx.y;
    const int s = blockIdx.x * 256 + threadIdx.x;
    __shared__ float A[1024];
    for (int l = threadIdx.x; l < 1024; l += 256)
        A[l] = g_attn[((size_t)(b * HEADS + h)) * 1024 + l];
    __syncthreads();

    const float* v = qkv + ((size_t)b * 384 + 256 + h * 32) * NSP;
    float acc[32] = {};
    #pragma unroll 4
    for (int cj = 0; cj < 32; cj++) {
        float vv = v[(size_t)cj * NSP + s];
        #pragma unroll
        for (int ci = 0; ci < 32; ci++) acc[ci] += A[ci * 32 + cj] * vv;
    }
    float* ob = out + ((size_t)b * 128 + h * 32) * NSP;
    #pragma unroll
    for (int ci = 0; ci < 32; ci++) ob[(size_t)ci * NSP + s] = acc[ci];
}

// ---------------- launch ----------------
extern "C" void kernel_launch(void* const* d_in, const int* in_sizes, int n_in,
                              void* d_out, int out_size) {
    const float* x      = (const float*)d_in[0];
    const float* qkv_r  = (const float*)d_in[1];
    const float* qkv_i  = (const float*)d_in[2];
    const float* qkv_j  = (const float*)d_in[3];
    const float* qkv_k  = (const float*)d_in[4];
    const float* qkv_b  = (const float*)d_in[5];
    const float* dw_r   = (const float*)d_in[6];
    const float* dw_i   = (const float*)d_in[7];
    const float* dw_j   = (const float*)d_in[8];
    const float* dw_k   = (const float*)d_in[9];
    const float* dw_b   = (const float*)d_in[10];
    const float* po_r   = (const float*)d_in[11];
    const float* po_i   = (const float*)d_in[12];
    const float* po_j   = (const float*)d_in[13];
    const float* po_k   = (const float*)d_in[14];
    const float* po_b   = (const float*)d_in[15];
    const float* temp   = (const float*)d_in[16];
    float* out = (float*)d_out;

    float *w_qkv, *w_dw, *w_po, *buf1, *buf2;
    cudaGetSymbolAddress((void**)&w_qkv, g_w_qkv);
    cudaGetSymbolAddress((void**)&w_dw,  g_w_dw);
    cudaGetSymbolAddress((void**)&w_po,  g_w_po);
    cudaGetSymbolAddress((void**)&buf1,  g_buf1);
    cudaGetSymbolAddress((void**)&buf2,  g_buf2);

    // 1) materialize quaternion weights
    build_weight<<<192, 256>>>(qkv_r, qkv_i, qkv_j, qkv_k, w_qkv, 96, 32, 1);
    build_weight<<<5184, 256>>>(dw_r, dw_i, dw_j, dw_k, w_dw, 96, 96, 9);
    build_weight<<<64, 256>>>(po_r, po_i, po_j, po_k, w_po, 32, 32, 1);

    // 2) qkv 1x1 conv: [B,128,NSP] -> [B,384,NSP]
    conv_mma<1, 0><<<dim3(NSP / 128, 3, BATCH), 256>>>(w_qkv, x, qkv_b, buf1, 384, 128);

    // 3) dw 3x3 conv: [B,384,NSP] -> [B,384,NSP]
    conv_mma<3, 1><<<dim3(NSP / 128, 3, BATCH), 256>>>(w_dw, buf1, dw_b, buf2, 384, 384);

    // 4) channel attention
    attn_partial<<<dim3(NCHUNK, HEADS, BATCH), 256>>>(buf2);
    attn_finalize<<<dim3(HEADS, BATCH), 32>>>(temp);
    attn_apply<<<dim3(NSP / 256, HEADS, BATCH), 256>>>(buf2, buf1);

    // 5) po 1x1 conv: [B,128,NSP] -> d_out
    conv_mma<1, 0><<<dim3(NSP / 128, 1, BATCH), 256>>>(w_po, buf1, po_b, out, 128, 128);
}

// round 13
// speedup vs baseline: 2.3063x; 1.0986x over previous
#include <cuda_runtime.h>
#include <cuda_bf16.h>
#include <math.h>
#include <stdint.h>

#define HWDIM 128
#define NSP   16384   // 128*128
#define BATCH 2
#define HEADS 4
#define NCHUNK 16
#define CHUNK  1024
#define TS     128

// ---------------- scratch (static device memory; no allocations) ----------------
// packed weights: [chunk][Cout][16] uint32 words, word = bf16x2 (k even lo, k odd hi)
__device__ uint32_t g_wqkv_h[4   * 384 * 16];
__device__ uint32_t g_wqkv_l[4   * 384 * 16];
__device__ uint32_t g_wdw_h [108 * 384 * 16];
__device__ uint32_t g_wdw_l [108 * 384 * 16];
__device__ uint32_t g_wpo_h [4   * 128 * 16];
__device__ uint32_t g_wpo_l [4   * 128 * 16];
__device__ float g_buf1[(size_t)BATCH * 384 * NSP];
__device__ float g_buf2[(size_t)BATCH * 384 * NSP];
__device__ float g_Gp [NCHUNK * BATCH * HEADS * 32 * 32];
__device__ float g_qnp[NCHUNK * BATCH * HEADS * 32];
__device__ float g_knp[NCHUNK * BATCH * HEADS * 32];
__device__ float g_attn[BATCH * HEADS * 32 * 32];

__constant__ int   c_cidx[16] = {0,1,2,3, 1,0,3,2, 2,3,0,1, 3,2,1,0};
__constant__ float c_sign[16] = {1,-1,-1,-1, 1,1,-1,1, 1,1,1,-1, 1,-1,1,1};

// ---------------- helpers ----------------
__device__ __forceinline__ uint32_t packbf(float a, float b) {
    __nv_bfloat162 t = __floats2bfloat162_rn(a, b);
    return *reinterpret_cast<uint32_t*>(&t);
}
__device__ __forceinline__ float bfres(float f) {
    return f - __bfloat162float(__float2bfloat16_rn(f));
}
__device__ __forceinline__ void mma_bf16(float* c, const uint32_t* a, const uint32_t* b) {
    asm volatile(
        "mma.sync.aligned.m16n8k16.row.col.f32.bf16.bf16.f32 "
        "{%0,%1,%2,%3}, {%4,%5,%6,%7}, {%8,%9}, {%0,%1,%2,%3};"
        : "+f"(c[0]), "+f"(c[1]), "+f"(c[2]), "+f"(c[3])
        : "r"(a[0]), "r"(a[1]), "r"(a[2]), "r"(a[3]), "r"(b[0]), "r"(b[1]));
}
__device__ __forceinline__ void cp16(uint32_t* dst, const uint32_t* src) {
    uint32_t d = (uint32_t)__cvta_generic_to_shared(dst);
    asm volatile("cp.async.cg.shared.global [%0], [%1], 16;" :: "r"(d), "l"(src));
}
#define CP_COMMIT() asm volatile("cp.async.commit_group;")
#define CP_WAIT0()  asm volatile("cp.async.wait_group 0;" ::: "memory")

// ---------------- build packed quaternion weight (bf16x2 hi/lo planes) ----------
// layout: word index = (c*Cout + m)*16 + kwl ; covers K columns, k-pairs packed.
__global__ void build_weight_pack(const float* __restrict__ r, const float* __restrict__ i,
                                  const float* __restrict__ j, const float* __restrict__ k,
                                  uint32_t* __restrict__ Wh, uint32_t* __restrict__ Wl,
                                  int Po, int Pi, int KHW) {
    const float* comps[4] = {r, i, j, k};
    const int Cout = 4 * Po;
    const int K = 4 * Pi * KHW;
    const int total = Cout * (K >> 1);
    for (int idx = blockIdx.x * blockDim.x + threadIdx.x; idx < total;
         idx += gridDim.x * blockDim.x) {
        int c   = idx / (Cout * 16);
        int rem = idx - c * Cout * 16;
        int m   = rem >> 4;
        int kwl = rem & 15;
        int k0  = c * 32 + kwl * 2;
        float w01[2];
        #pragma unroll
        for (int e = 0; e < 2; e++) {
            int kcol = k0 + e;
            int cc = kcol / KHW, khw = kcol - cc * KHW;
            int t = (m / Po) * 4 + (cc / Pi);
            w01[e] = c_sign[t] * comps[c_cidx[t]][((m % Po) * Pi + (cc % Pi)) * KHW + khw];
        }
        Wh[idx] = packbf(w01[0], w01[1]);
        Wl[idx] = packbf(bfres(w01[0]), bfres(w01[1]));
    }
}

// ---------------- bf16x3-split implicit-GEMM conv, pipelined ----------------
// C[m,n] = sum_k W[m,k]*im2col(X)[k,n] + bias[m];  acc = Wh*Xh + Wh*Xl + Wl*Xh
// CTA 128m x 64n x 32k chunks; 8 warps (2m x 4n), warp tile 64x16, m16n8k16.
// A: prepacked bf16, cp.async double-buffered. B: LDG fp32 -> cvt -> STS, double-buffered.
// ONE __syncthreads per chunk.
#define A_STW 20      // words per A row: 16 + 4 pad
#define B_STW 72      // words per B kw-row: 64 n + 8 pad
#define A_PLANE 2560  // 128 * A_STW words
#define B_PLANE 1152  // 16 * B_STW words
#define SMEM_WORDS (4 * A_PLANE + 4 * B_PLANE)   // 14848 words = 59392 B

template <int KS, int PAD>
__global__ void __launch_bounds__(256, 2)
conv_mma(const uint32_t* __restrict__ Wh, const uint32_t* __restrict__ Wl,
         const float* __restrict__ in, const float* __restrict__ bias,
         float* __restrict__ out, int Cout, int Cin) {
    extern __shared__ uint32_t sm[];
    const int K  = Cin * KS * KS;
    const int NC = K / 32;
    const int b  = blockIdx.z;
    const int m0 = blockIdx.y * 128, n0 = blockIdx.x * 64;
    const float* inb = in + (size_t)b * Cin * NSP;

    const int tid  = threadIdx.x;
    const int w    = tid >> 5, lane = tid & 31;
    const int gid  = lane >> 2, tig = lane & 3;
    const int mw   = (w >> 2) * 64;   // warp m offset (0/64)
    const int nw   = (w & 3) * 16;    // warp n offset

    // B loader indexing: one thread = (kw row, 4 n)
    const int kwl = tid >> 4;          // 0..15
    const int nf4 = (tid & 15) * 4;    // 0..60

    float fB[2][4];   // B prefetch fp32: [k parity][n]

    auto loadA = [&](int c, int s) {
        const uint32_t* srcH = Wh + ((size_t)c * Cout + m0) * 16;
        const uint32_t* srcL = Wl + ((size_t)c * Cout + m0) * 16;
        uint32_t* dH = sm + (s * 2 + 0) * A_PLANE;
        uint32_t* dL = sm + (s * 2 + 1) * A_PLANE;
        #pragma unroll
        for (int i2 = 0; i2 < 2; i2++) {
            int u = tid * 2 + i2;          // 0..511 16B-chunks
            int row = u >> 2, sub = (u & 3) * 4;
            cp16(dH + row * A_STW + sub, srcH + row * 16 + sub);
            cp16(dL + row * A_STW + sub, srcL + row * 16 + sub);
        }
    };

    auto loadB = [&](int k0) {
        #pragma unroll
        for (int kp = 0; kp < 2; kp++) {
            int kk = k0 + kwl * 2 + kp;
            if (KS == 1) {
                float4 xv = *(const float4*)&inb[(size_t)kk * NSP + n0 + nf4];
                fB[kp][0] = xv.x; fB[kp][1] = xv.y; fB[kp][2] = xv.z; fB[kp][3] = xv.w;
            } else {
                int cch = kk / 9;
                int rem = kk - cch * 9;
                int ky = rem / 3, kx = rem - ky * 3;
                int n = n0 + nf4;
                int y = n >> 7, x = n & 127;
                int iy = y + ky - PAD;
                bool yok = (unsigned)iy < (unsigned)HWDIM;
                const float* rowp = inb + ((size_t)cch << 14) + ((size_t)iy << 7);
                int ix0 = x + kx - PAD;
                #pragma unroll
                for (int i2 = 0; i2 < 4; i2++)
                    fB[kp][i2] = (yok && (unsigned)(ix0 + i2) < 128u)
                                     ? __ldg(rowp + ix0 + i2) : 0.f;
            }
        }
    };

    auto stsB = [&](int s) {
        uint32_t* dH = sm + 4 * A_PLANE + (s * 2 + 0) * B_PLANE;
        uint32_t* dL = sm + 4 * A_PLANE + (s * 2 + 1) * B_PLANE;
        uint4 hw, lw;
        hw.x = packbf(fB[0][0], fB[1][0]);
        hw.y = packbf(fB[0][1], fB[1][1]);
        hw.z = packbf(fB[0][2], fB[1][2]);
        hw.w = packbf(fB[0][3], fB[1][3]);
        lw.x = packbf(bfres(fB[0][0]), bfres(fB[1][0]));
        lw.y = packbf(bfres(fB[0][1]), bfres(fB[1][1]));
        lw.z = packbf(bfres(fB[0][2]), bfres(fB[1][2]));
        lw.w = packbf(bfres(fB[0][3]), bfres(fB[1][3]));
        *(uint4*)&dH[kwl * B_STW + nf4] = hw;
        *(uint4*)&dL[kwl * B_STW + nf4] = lw;
    };

    float acc[4][2][4] = {};

    // prologue: fill stage 0
    loadA(0, 0);
    CP_COMMIT();
    loadB(0);
    stsB(0);
    CP_WAIT0();
    __syncthreads();

    for (int c = 0; c < NC; c++) {
        const int s = c & 1;
        const bool more = (c + 1 < NC);
        if (more) {
            loadA(c + 1, s ^ 1);
            CP_COMMIT();
            loadB((c + 1) * 32);
        }

        const uint32_t* AsH = sm + (s * 2 + 0) * A_PLANE;
        const uint32_t* AsL = sm + (s * 2 + 1) * A_PLANE;
        const uint32_t* BsH = sm + 4 * A_PLANE + (s * 2 + 0) * B_PLANE;
        const uint32_t* BsL = sm + 4 * A_PLANE + (s * 2 + 1) * B_PLANE;

        #pragma unroll
        for (int ks = 0; ks < 2; ks++) {
            const int kw0 = ks * 8;
            uint32_t ah[4][4], al[4][4], bh[2][2], bl[2][2];
            #pragma unroll
            for (int mt = 0; mt < 4; mt++) {
                int r0 = (mw + mt * 16 + gid) * A_STW;
                int r8 = r0 + 8 * A_STW;
                ah[mt][0] = AsH[r0 + kw0 + tig];
                ah[mt][1] = AsH[r8 + kw0 + tig];
                ah[mt][2] = AsH[r0 + kw0 + tig + 4];
                ah[mt][3] = AsH[r8 + kw0 + tig + 4];
                al[mt][0] = AsL[r0 + kw0 + tig];
                al[mt][1] = AsL[r8 + kw0 + tig];
                al[mt][2] = AsL[r0 + kw0 + tig + 4];
                al[mt][3] = AsL[r8 + kw0 + tig + 4];
            }
            #pragma unroll
            for (int nt = 0; nt < 2; nt++) {
                int nc0 = nw + nt * 8 + gid;
                bh[nt][0] = BsH[(kw0 + tig) * B_STW + nc0];
                bh[nt][1] = BsH[(kw0 + tig + 4) * B_STW + nc0];
                bl[nt][0] = BsL[(kw0 + tig) * B_STW + nc0];
                bl[nt][1] = BsL[(kw0 + tig + 4) * B_STW + nc0];
            }
            #pragma unroll
            for (int mt = 0; mt < 4; mt++)
                #pragma unroll
                for (int nt = 0; nt < 2; nt++) {
                    mma_bf16(acc[mt][nt], ah[mt], bh[nt]);
                    mma_bf16(acc[mt][nt], ah[mt], bl[nt]);
                    mma_bf16(acc[mt][nt], al[mt], bh[nt]);
                }
        }

        if (more) stsB(s ^ 1);
        CP_WAIT0();
        __syncthreads();
    }

    // epilogue: direct fragment stores (+bias)
    float* outb = out + (size_t)b * Cout * NSP;
    #pragma unroll
    for (int mt = 0; mt < 4; mt++) {
        int m = m0 + mw + mt * 16 + gid;
        float bs0 = bias[m], bs1 = bias[m + 8];
        #pragma unroll
        for (int nt = 0; nt < 2; nt++) {
            int n = n0 + nw + nt * 8 + tig * 2;
            float2 v0 = make_float2(acc[mt][nt][0] + bs0, acc[mt][nt][1] + bs0);
            float2 v1 = make_float2(acc[mt][nt][2] + bs1, acc[mt][nt][3] + bs1);
            *(float2*)&outb[(size_t)m * NSP + n]       = v0;
            *(float2*)&outb[(size_t)(m + 8) * NSP + n] = v1;
        }
    }
}

// ---------------- attention stage 1: partial Gram + norms (deterministic) ------
__global__ void attn_partial(const float* __restrict__ qkv) {
    const int b = blockIdx.z, h = blockIdx.y, chunk = blockIdx.x;
    const float* q = qkv + ((size_t)b * 384 + h * 32) * NSP;
    const float* k = qkv + ((size_t)b * 384 + 128 + h * 32) * NSP;

    __shared__ float qs[32][TS + 1];
    __shared__ float ks[32][TS + 1];

    const int tid = threadIdx.x;
    const int e0 = tid * 4;
    const int ci = e0 >> 5;
    const int cj0 = e0 & 31;

    float acc[4] = {};
    float qn = 0.f, kn = 0.f;
    const int sbase0 = chunk * CHUNK;

    for (int t = 0; t < CHUNK / TS; t++) {
        int sbase = sbase0 + t * TS;
        for (int l = tid; l < 32 * TS; l += 256) {
            int c = l / TS, ss = l % TS;
            qs[c][ss] = q[(size_t)c * NSP + sbase + ss];
            ks[c][ss] = k[(size_t)c * NSP + sbase + ss];
        }
        __syncthreads();
        #pragma unroll 4
        for (int ss = 0; ss < TS; ss++) {
            float qv = qs[ci][ss];
            acc[0] += qv * ks[cj0 + 0][ss];
            acc[1] += qv * ks[cj0 + 1][ss];
            acc[2] += qv * ks[cj0 + 2][ss];
            acc[3] += qv * ks[cj0 + 3][ss];
        }
        if (tid < 32) {
            for (int ss = 0; ss < TS; ss++) {
                float a = qs[tid][ss]; qn += a * a;
                float c2 = ks[tid][ss]; kn += c2 * c2;
            }
        }
        __syncthreads();
    }

    int bh = b * HEADS + h;
    float* Gp = g_Gp + ((size_t)chunk * BATCH * HEADS + bh) * 1024;
    Gp[e0 + 0] = acc[0]; Gp[e0 + 1] = acc[1];
    Gp[e0 + 2] = acc[2]; Gp[e0 + 3] = acc[3];
    if (tid < 32) {
        g_qnp[((size_t)chunk * BATCH * HEADS + bh) * 32 + tid] = qn;
        g_knp[((size_t)chunk * BATCH * HEADS + bh) * 32 + tid] = kn;
    }
}

// ---------------- attention stage 2: reduce, normalize, softmax ----------------
__global__ void attn_finalize(const float* __restrict__ temperature) {
    const int b = blockIdx.y, h = blockIdx.x;
    const int bh = b * HEADS + h;
    const int ci = threadIdx.x;

    __shared__ float qn_s[32], kn_s[32];
    float qn = 0.f, kn = 0.f;
    for (int c = 0; c < NCHUNK; c++) {
        qn += g_qnp[((size_t)c * BATCH * HEADS + bh) * 32 + ci];
        kn += g_knp[((size_t)c * BATCH * HEADS + bh) * 32 + ci];
    }
    qn_s[ci] = fmaxf(sqrtf(qn), 1e-12f);
    kn_s[ci] = fmaxf(sqrtf(kn), 1e-12f);
    __syncwarp();

    float T = temperature[h];
    float qi = qn_s[ci];
    float lg[32];
    float mx = -1e30f;
    #pragma unroll
    for (int cj = 0; cj < 32; cj++) {
        float g = 0.f;
        for (int c = 0; c < NCHUNK; c++)
            g += g_Gp[(((size_t)c * BATCH * HEADS + bh) * 1024) + ci * 32 + cj];
        float v = g / (qi * kn_s[cj]) * T;
        lg[cj] = v;
        mx = fmaxf(mx, v);
    }
    float s = 0.f;
    #pragma unroll
    for (int cj = 0; cj < 32; cj++) { lg[cj] = __expf(lg[cj] - mx); s += lg[cj]; }
    float inv = 1.f / s;
    float* A = g_attn + (size_t)bh * 1024;
    #pragma unroll
    for (int cj = 0; cj < 32; cj++) A[ci * 32 + cj] = lg[cj] * inv;
}

// ---------------- attention stage 3: out = attn @ v ----------------
__global__ void attn_apply(const float* __restrict__ qkv, float* __restrict__ out) {
    const int b = blockIdx.z, h = blockIdx.y;
    const int s = blockIdx.x * 256 + threadIdx.x;
    __shared__ float A[1024];
    for (int l = threadIdx.x; l < 1024; l += 256)
        A[l] = g_attn[((size_t)(b * HEADS + h)) * 1024 + l];
    __syncthreads();

    const float* v = qkv + ((size_t)b * 384 + 256 + h * 32) * NSP;
    float acc[32] = {};
    #pragma unroll 4
    for (int cj = 0; cj < 32; cj++) {
        float vv = v[(size_t)cj * NSP + s];
        #pragma unroll
        for (int ci = 0; ci < 32; ci++) acc[ci] += A[ci * 32 + cj] * vv;
    }
    float* ob = out + ((size_t)b * 128 + h * 32) * NSP;
    #pragma unroll
    for (int ci = 0; ci < 32; ci++) ob[(size_t)ci * NSP + s] = acc[ci];
}

// ---------------- launch ----------------
extern "C" void kernel_launch(void* const* d_in, const int* in_sizes, int n_in,
                              void* d_out, int out_size) {
    const float* x      = (const float*)d_in[0];
    const float* qkv_r  = (const float*)d_in[1];
    const float* qkv_i  = (const float*)d_in[2];
    const float* qkv_j  = (const float*)d_in[3];
    const float* qkv_k  = (const float*)d_in[4];
    const float* qkv_b  = (const float*)d_in[5];
    const float* dw_r   = (const float*)d_in[6];
    const float* dw_i   = (const float*)d_in[7];
    const float* dw_j   = (const float*)d_in[8];
    const float* dw_k   = (const float*)d_in[9];
    const float* dw_b   = (const float*)d_in[10];
    const float* po_r   = (const float*)d_in[11];
    const float* po_i   = (const float*)d_in[12];
    const float* po_j   = (const float*)d_in[13];
    const float* po_k   = (const float*)d_in[14];
    const float* po_b   = (const float*)d_in[15];
    const float* temp   = (const float*)d_in[16];
    float* out = (float*)d_out;

    uint32_t *wqh, *wql, *wdh, *wdl, *wph, *wpl;
    float *buf1, *buf2;
    cudaGetSymbolAddress((void**)&wqh, g_wqkv_h);
    cudaGetSymbolAddress((void**)&wql, g_wqkv_l);
    cudaGetSymbolAddress((void**)&wdh, g_wdw_h);
    cudaGetSymbolAddress((void**)&wdl, g_wdw_l);
    cudaGetSymbolAddress((void**)&wph, g_wpo_h);
    cudaGetSymbolAddress((void**)&wpl, g_wpo_l);
    cudaGetSymbolAddress((void**)&buf1, g_buf1);
    cudaGetSymbolAddress((void**)&buf2, g_buf2);

    const int smem_bytes = SMEM_WORDS * 4;
    cudaFuncSetAttribute(conv_mma<1, 0>, cudaFuncAttributeMaxDynamicSharedMemorySize, smem_bytes);
    cudaFuncSetAttribute(conv_mma<3, 1>, cudaFuncAttributeMaxDynamicSharedMemorySize, smem_bytes);

    // 1) materialize packed quaternion weights (bf16x2 hi/lo, MMA layout)
    build_weight_pack<<<96, 256>>>(qkv_r, qkv_i, qkv_j, qkv_k, wqh, wql, 96, 32, 1);
    build_weight_pack<<<2592, 256>>>(dw_r, dw_i, dw_j, dw_k, wdh, wdl, 96, 96, 9);
    build_weight_pack<<<32, 256>>>(po_r, po_i, po_j, po_k, wph, wpl, 32, 32, 1);

    // 2) qkv 1x1 conv: [B,128,NSP] -> [B,384,NSP]
    conv_mma<1, 0><<<dim3(NSP / 64, 3, BATCH), 256, smem_bytes>>>(wqh, wql, x, qkv_b, buf1, 384, 128);

    // 3) dw 3x3 conv: [B,384,NSP] -> [B,384,NSP]
    conv_mma<3, 1><<<dim3(NSP / 64, 3, BATCH), 256, smem_bytes>>>(wdh, wdl, buf1, dw_b, buf2, 384, 384);

    // 4) channel attention
    attn_partial<<<dim3(NCHUNK, HEADS, BATCH), 256>>>(buf2);
    attn_finalize<<<dim3(HEADS, BATCH), 32>>>(temp);
    attn_apply<<<dim3(NSP / 256, HEADS, BATCH), 256>>>(buf2, buf1);

    // 5) po 1x1 conv: [B,128,NSP] -> d_out
    conv_mma<1, 0><<<dim3(NSP / 64, 1, BATCH), 256, smem_bytes>>>(wph, wpl, buf1, po_b, out, 128, 128);
}

// round 14
// speedup vs baseline: 2.3969x; 1.0393x over previous
#include <cuda_runtime.h>
#include <cuda_bf16.h>
#include <math.h>
#include <stdint.h>

#define HWDIM 128
#define NSP   16384   // 128*128
#define BATCH 2
#define HEADS 4
#define NCHUNK 16
#define CHUNK  1024
#define TS     128

// ---------------- scratch (static device memory; no allocations) ----------------
// packed weights: [chunk][Cout][16] uint32 words, word = bf16x2 (k even lo, k odd hi)
__device__ uint32_t g_wqkv_h[4   * 384 * 16];
__device__ uint32_t g_wqkv_l[4   * 384 * 16];
__device__ uint32_t g_wdw_h [108 * 384 * 16];
__device__ uint32_t g_wdw_l [108 * 384 * 16];
__device__ uint32_t g_wpo_h [4   * 128 * 16];
__device__ uint32_t g_wpo_l [4   * 128 * 16];
__device__ float g_buf1[(size_t)BATCH * 384 * NSP];
__device__ float g_buf2[(size_t)BATCH * 384 * NSP];
__device__ float g_Gp [NCHUNK * BATCH * HEADS * 32 * 32];
__device__ float g_qnp[NCHUNK * BATCH * HEADS * 32];
__device__ float g_knp[NCHUNK * BATCH * HEADS * 32];
__device__ float g_attn[BATCH * HEADS * 32 * 32];

__constant__ int   c_cidx[16] = {0,1,2,3, 1,0,3,2, 2,3,0,1, 3,2,1,0};
__constant__ float c_sign[16] = {1,-1,-1,-1, 1,1,-1,1, 1,1,1,-1, 1,-1,1,1};

// ---------------- helpers ----------------
__device__ __forceinline__ uint32_t packbf(float a, float b) {
    __nv_bfloat162 t = __floats2bfloat162_rn(a, b);
    return *reinterpret_cast<uint32_t*>(&t);
}
__device__ __forceinline__ float bfres(float f) {
    return f - __bfloat162float(__float2bfloat16_rn(f));
}
__device__ __forceinline__ void mma_bf16(float* c, const uint32_t* a, const uint32_t* b) {
    asm volatile(
        "mma.sync.aligned.m16n8k16.row.col.f32.bf16.bf16.f32 "
        "{%0,%1,%2,%3}, {%4,%5,%6,%7}, {%8,%9}, {%0,%1,%2,%3};"
        : "+f"(c[0]), "+f"(c[1]), "+f"(c[2]), "+f"(c[3])
        : "r"(a[0]), "r"(a[1]), "r"(a[2]), "r"(a[3]), "r"(b[0]), "r"(b[1]));
}
__device__ __forceinline__ void ldm_x4(uint32_t* r, uint32_t saddr) {
    asm volatile("ldmatrix.sync.aligned.m8n8.x4.shared.b16 {%0,%1,%2,%3}, [%4];"
        : "=r"(r[0]), "=r"(r[1]), "=r"(r[2]), "=r"(r[3]) : "r"(saddr));
}
__device__ __forceinline__ void cp16(uint32_t* dst, const uint32_t* src) {
    uint32_t d = (uint32_t)__cvta_generic_to_shared(dst);
    asm volatile("cp.async.cg.shared.global [%0], [%1], 16;" :: "r"(d), "l"(src));
}
#define CP_COMMIT() asm volatile("cp.async.commit_group;")
#define CP_WAIT0()  asm volatile("cp.async.wait_group 0;" ::: "memory")

// ---------------- build packed quaternion weight (bf16x2 hi/lo planes) ----------
__global__ void build_weight_pack(const float* __restrict__ r, const float* __restrict__ i,
                                  const float* __restrict__ j, const float* __restrict__ k,
                                  uint32_t* __restrict__ Wh, uint32_t* __restrict__ Wl,
                                  int Po, int Pi, int KHW) {
    const float* comps[4] = {r, i, j, k};
    const int Cout = 4 * Po;
    const int K = 4 * Pi * KHW;
    const int total = Cout * (K >> 1);
    for (int idx = blockIdx.x * blockDim.x + threadIdx.x; idx < total;
         idx += gridDim.x * blockDim.x) {
        int c   = idx / (Cout * 16);
        int rem = idx - c * Cout * 16;
        int m   = rem >> 4;
        int kwl = rem & 15;
        int k0  = c * 32 + kwl * 2;
        float w01[2];
        #pragma unroll
        for (int e = 0; e < 2; e++) {
            int kcol = k0 + e;
            int cc = kcol / KHW, khw = kcol - cc * KHW;
            int t = (m / Po) * 4 + (cc / Pi);
            w01[e] = c_sign[t] * comps[c_cidx[t]][((m % Po) * Pi + (cc % Pi)) * KHW + khw];
        }
        Wh[idx] = packbf(w01[0], w01[1]);
        Wl[idx] = packbf(bfres(w01[0]), bfres(w01[1]));
    }
}

// ---------------- bf16x3-split implicit-GEMM conv, pipelined ----------------
// acc = Wh*Xh + Wh*Xl + Wl*Xh ; CTA 128m x 64n x 32k chunks; 8 warps (2m x 4n).
// A: prepacked bf16 via cp.async, fragments via ldmatrix.x4 (conflict-free).
// B: LDG fp32 -> cvt -> STS, double-buffered. MMA ordered term-outer so
// accumulator reuse distance is 8 (no serial HMMA chains).
#define A_STW 20      // words per A row: 16 + 4 pad
#define B_STW 72      // words per B kw-row: 64 n + 8 pad
#define A_PLANE 2560  // 128 * A_STW words
#define B_PLANE 1152  // 16 * B_STW words
#define SMEM_WORDS (4 * A_PLANE + 4 * B_PLANE)   // 59392 B

template <int KS, int PAD>
__global__ void __launch_bounds__(256, 2)
conv_mma(const uint32_t* __restrict__ Wh, const uint32_t* __restrict__ Wl,
         const float* __restrict__ in, const float* __restrict__ bias,
         float* __restrict__ out, int Cout, int Cin) {
    extern __shared__ uint32_t sm[];
    const int K  = Cin * KS * KS;
    const int NC = K / 32;
    const int b  = blockIdx.z;
    const int m0 = blockIdx.y * 128, n0 = blockIdx.x * 64;
    const float* inb = in + (size_t)b * Cin * NSP;

    const int tid  = threadIdx.x;
    const int w    = tid >> 5, lane = tid & 31;
    const int gid  = lane >> 2, tig = lane & 3;
    const int mw   = (w >> 2) * 64;   // warp m offset (0/64)
    const int nw   = (w & 3) * 16;    // warp n offset

    // B loader indexing: one thread = (kw row, 4 n)
    const int kwl = tid >> 4;          // 0..15
    const int nf4 = (tid & 15) * 4;    // 0..60

    // ldmatrix lane address: group g supplies rows of matrix g
    const uint32_t sm_u32 = (uint32_t)__cvta_generic_to_shared(sm);
    const int lg = lane >> 3, lr = lane & 7;
    const uint32_t a_lane_off =
        (((mw + (lg & 1) * 8 + lr) * A_STW) + (lg >> 1) * 4) * 4;  // bytes

    float fB[2][4];   // B prefetch fp32: [k parity][n]

    auto loadA = [&](int c, int s) {
        const uint32_t* srcH = Wh + ((size_t)c * Cout + m0) * 16;
        const uint32_t* srcL = Wl + ((size_t)c * Cout + m0) * 16;
        uint32_t* dH = sm + (s * 2 + 0) * A_PLANE;
        uint32_t* dL = sm + (s * 2 + 1) * A_PLANE;
        #pragma unroll
        for (int i2 = 0; i2 < 2; i2++) {
            int u = tid * 2 + i2;          // 0..511 16B-chunks
            int row = u >> 2, sub = (u & 3) * 4;
            cp16(dH + row * A_STW + sub, srcH + row * 16 + sub);
            cp16(dL + row * A_STW + sub, srcL + row * 16 + sub);
        }
    };

    auto loadB = [&](int k0) {
        #pragma unroll
        for (int kp = 0; kp < 2; kp++) {
            int kk = k0 + kwl * 2 + kp;
            if (KS == 1) {
                float4 xv = *(const float4*)&inb[(size_t)kk * NSP + n0 + nf4];
                fB[kp][0] = xv.x; fB[kp][1] = xv.y; fB[kp][2] = xv.z; fB[kp][3] = xv.w;
            } else {
                int cch = kk / 9;
                int rem = kk - cch * 9;
                int ky = rem / 3, kx = rem - ky * 3;
                int n = n0 + nf4;
                int y = n >> 7, x = n & 127;
                int iy = y + ky - PAD;
                bool yok = (unsigned)iy < (unsigned)HWDIM;
                const float* rowp = inb + ((size_t)cch << 14) + ((size_t)iy << 7);
                int ix0 = x + kx - PAD;
                #pragma unroll
                for (int i2 = 0; i2 < 4; i2++)
                    fB[kp][i2] = (yok && (unsigned)(ix0 + i2) < 128u)
                                     ? __ldg(rowp + ix0 + i2) : 0.f;
            }
        }
    };

    auto stsB = [&](int s) {
        uint32_t* dH = sm + 4 * A_PLANE + (s * 2 + 0) * B_PLANE;
        uint32_t* dL = sm + 4 * A_PLANE + (s * 2 + 1) * B_PLANE;
        uint4 hw, lw;
        hw.x = packbf(fB[0][0], fB[1][0]);
        hw.y = packbf(fB[0][1], fB[1][1]);
        hw.z = packbf(fB[0][2], fB[1][2]);
        hw.w = packbf(fB[0][3], fB[1][3]);
        lw.x = packbf(bfres(fB[0][0]), bfres(fB[1][0]));
        lw.y = packbf(bfres(fB[0][1]), bfres(fB[1][1]));
        lw.z = packbf(bfres(fB[0][2]), bfres(fB[1][2]));
        lw.w = packbf(bfres(fB[0][3]), bfres(fB[1][3]));
        *(uint4*)&dH[kwl * B_STW + nf4] = hw;
        *(uint4*)&dL[kwl * B_STW + nf4] = lw;
    };

    float acc[4][2][4] = {};

    // prologue: fill stage 0
    loadA(0, 0);
    CP_COMMIT();
    loadB(0);
    stsB(0);
    CP_WAIT0();
    __syncthreads();

    for (int c = 0; c < NC; c++) {
        const int s = c & 1;
        const bool more = (c + 1 < NC);
        if (more) {
            loadA(c + 1, s ^ 1);
            CP_COMMIT();
            loadB((c + 1) * 32);
        }

        const uint32_t aH32 = sm_u32 + (s * 2 + 0) * A_PLANE * 4;
        const uint32_t aL32 = sm_u32 + (s * 2 + 1) * A_PLANE * 4;
        const uint32_t* BsH = sm + 4 * A_PLANE + (s * 2 + 0) * B_PLANE;
        const uint32_t* BsL = sm + 4 * A_PLANE + (s * 2 + 1) * B_PLANE;

        #pragma unroll
        for (int ks = 0; ks < 2; ks++) {
            const int kw0 = ks * 8;
            uint32_t ah[4][4], al[4][4], bh[2][2], bl[2][2];
            #pragma unroll
            for (int mt = 0; mt < 4; mt++) {
                uint32_t off = a_lane_off + mt * (16 * A_STW * 4) + kw0 * 4;
                ldm_x4(ah[mt], aH32 + off);
                ldm_x4(al[mt], aL32 + off);
            }
            #pragma unroll
            for (int nt = 0; nt < 2; nt++) {
                int nc0 = nw + nt * 8 + gid;
                bh[nt][0] = BsH[(kw0 + tig) * B_STW + nc0];
                bh[nt][1] = BsH[(kw0 + tig + 4) * B_STW + nc0];
                bl[nt][0] = BsL[(kw0 + tig) * B_STW + nc0];
                bl[nt][1] = BsL[(kw0 + tig + 4) * B_STW + nc0];
            }
            // term-outer ordering: accumulator reuse distance = 8 MMAs
            #pragma unroll
            for (int mt = 0; mt < 4; mt++)
                #pragma unroll
                for (int nt = 0; nt < 2; nt++)
                    mma_bf16(acc[mt][nt], ah[mt], bh[nt]);
            #pragma unroll
            for (int mt = 0; mt < 4; mt++)
                #pragma unroll
                for (int nt = 0; nt < 2; nt++)
                    mma_bf16(acc[mt][nt], ah[mt], bl[nt]);
            #pragma unroll
            for (int mt = 0; mt < 4; mt++)
                #pragma unroll
                for (int nt = 0; nt < 2; nt++)
                    mma_bf16(acc[mt][nt], al[mt], bh[nt]);
        }

        if (more) stsB(s ^ 1);
        CP_WAIT0();
        __syncthreads();
    }

    // epilogue: direct fragment stores (+bias)
    float* outb = out + (size_t)b * Cout * NSP;
    #pragma unroll
    for (int mt = 0; mt < 4; mt++) {
        int m = m0 + mw + mt * 16 + gid;
        float bs0 = bias[m], bs1 = bias[m + 8];
        #pragma unroll
        for (int nt = 0; nt < 2; nt++) {
            int n = n0 + nw + nt * 8 + tig * 2;
            float2 v0 = make_float2(acc[mt][nt][0] + bs0, acc[mt][nt][1] + bs0);
            float2 v1 = make_float2(acc[mt][nt][2] + bs1, acc[mt][nt][3] + bs1);
            *(float2*)&outb[(size_t)m * NSP + n]       = v0;
            *(float2*)&outb[(size_t)(m + 8) * NSP + n] = v1;
        }
    }
}

// ---------------- attention stage 1: partial Gram + norms (deterministic) ------
__global__ void attn_partial(const float* __restrict__ qkv) {
    const int b = blockIdx.z, h = blockIdx.y, chunk = blockIdx.x;
    const float* q = qkv + ((size_t)b * 384 + h * 32) * NSP;
    const float* k = qkv + ((size_t)b * 384 + 128 + h * 32) * NSP;

    __shared__ float qs[32][TS + 1];
    __shared__ float ks[32][TS + 1];

    const int tid = threadIdx.x;
    const int e0 = tid * 4;
    const int ci = e0 >> 5;
    const int cj0 = e0 & 31;

    float acc[4] = {};
    float qn = 0.f, kn = 0.f;
    const int sbase0 = chunk * CHUNK;

    for (int t = 0; t < CHUNK / TS; t++) {
        int sbase = sbase0 + t * TS;
        for (int l = tid; l < 32 * TS; l += 256) {
            int c = l / TS, ss = l % TS;
            qs[c][ss] = q[(size_t)c * NSP + sbase + ss];
            ks[c][ss] = k[(size_t)c * NSP + sbase + ss];
        }
        __syncthreads();
        #pragma unroll 4
        for (int ss = 0; ss < TS; ss++) {
            float qv = qs[ci][ss];
            acc[0] += qv * ks[cj0 + 0][ss];
            acc[1] += qv * ks[cj0 + 1][ss];
            acc[2] += qv * ks[cj0 + 2][ss];
            acc[3] += qv * ks[cj0 + 3][ss];
        }
        if (tid < 32) {
            for (int ss = 0; ss < TS; ss++) {
                float a = qs[tid][ss]; qn += a * a;
                float c2 = ks[tid][ss]; kn += c2 * c2;
            }
        }
        __syncthreads();
    }

    int bh = b * HEADS + h;
    float* Gp = g_Gp + ((size_t)chunk * BATCH * HEADS + bh) * 1024;
    Gp[e0 + 0] = acc[0]; Gp[e0 + 1] = acc[1];
    Gp[e0 + 2] = acc[2]; Gp[e0 + 3] = acc[3];
    if (tid < 32) {
        g_qnp[((size_t)chunk * BATCH * HEADS + bh) * 32 + tid] = qn;
        g_knp[((size_t)chunk * BATCH * HEADS + bh) * 32 + tid] = kn;
    }
}

// ---------------- attention stage 2: reduce, normalize, softmax ----------------
__global__ void attn_finalize(const float* __restrict__ temperature) {
    const int b = blockIdx.y, h = blockIdx.x;
    const int bh = b * HEADS + h;
    const int ci = threadIdx.x;

    __shared__ float qn_s[32], kn_s[32];
    float qn = 0.f, kn = 0.f;
    for (int c = 0; c < NCHUNK; c++) {
        qn += g_qnp[((size_t)c * BATCH * HEADS + bh) * 32 + ci];
        kn += g_knp[((size_t)c * BATCH * HEADS + bh) * 32 + ci];
    }
    qn_s[ci] = fmaxf(sqrtf(qn), 1e-12f);
    kn_s[ci] = fmaxf(sqrtf(kn), 1e-12f);
    __syncwarp();

    float T = temperature[h];
    float qi = qn_s[ci];
    float lg[32];
    float mx = -1e30f;
    #pragma unroll
    for (int cj = 0; cj < 32; cj++) {
        float g = 0.f;
        for (int c = 0; c < NCHUNK; c++)
            g += g_Gp[(((size_t)c * BATCH * HEADS + bh) * 1024) + ci * 32 + cj];
        float v = g / (qi * kn_s[cj]) * T;
        lg[cj] = v;
        mx = fmaxf(mx, v);
    }
    float s = 0.f;
    #pragma unroll
    for (int cj = 0; cj < 32; cj++) { lg[cj] = __expf(lg[cj] - mx); s += lg[cj]; }
    float inv = 1.f / s;
    float* A = g_attn + (size_t)bh * 1024;
    #pragma unroll
    for (int cj = 0; cj < 32; cj++) A[ci * 32 + cj] = lg[cj] * inv;
}

// ---------------- attention stage 3: out = attn @ v ----------------
__global__ void attn_apply(const float* __restrict__ qkv, float* __restrict__ out) {
    const int b = blockIdx.z, h = blockIdx.y;
    const int s = blockIdx.x * 256 + threadIdx.x;
    __shared__ float A[1024];
    for (int l = threadIdx.x; l < 1024; l += 256)
        A[l] = g_attn[((size_t)(b * HEADS + h)) * 1024 + l];
    __syncthreads();

    const float* v = qkv + ((size_t)b * 384 + 256 + h * 32) * NSP;
    float acc[32] = {};
    #pragma unroll 4
    for (int cj = 0; cj < 32; cj++) {
        float vv = v[(size_t)cj * NSP + s];
        #pragma unroll
        for (int ci = 0; ci < 32; ci++) acc[ci] += A[ci * 32 + cj] * vv;
    }
    float* ob = out + ((size_t)b * 128 + h * 32) * NSP;
    #pragma unroll
    for (int ci = 0; ci < 32; ci++) ob[(size_t)ci * NSP + s] = acc[ci];
}

// ---------------- launch ----------------
extern "C" void kernel_launch(void* const* d_in, const int* in_sizes, int n_in,
                              void* d_out, int out_size) {
    const float* x      = (const float*)d_in[0];
    const float* qkv_r  = (const float*)d_in[1];
    const float* qkv_i  = (const float*)d_in[2];
    const float* qkv_j  = (const float*)d_in[3];
    const float* qkv_k  = (const float*)d_in[4];
    const float* qkv_b  = (const float*)d_in[5];
    const float* dw_r   = (const float*)d_in[6];
    const float* dw_i   = (const float*)d_in[7];
    const float* dw_j   = (const float*)d_in[8];
    const float* dw_k   = (const float*)d_in[9];
    const float* dw_b   = (const float*)d_in[10];
    const float* po_r   = (const float*)d_in[11];
    const float* po_i   = (const float*)d_in[12];
    const float* po_j   = (const float*)d_in[13];
    const float* po_k   = (const float*)d_in[14];
    const float* po_b   = (const float*)d_in[15];
    const float* temp   = (const float*)d_in[16];
    float* out = (float*)d_out;

    uint32_t *wqh, *wql, *wdh, *wdl, *wph, *wpl;
    float *buf1, *buf2;
    cudaGetSymbolAddress((void**)&wqh, g_wqkv_h);
    cudaGetSymbolAddress((void**)&wql, g_wqkv_l);
    cudaGetSymbolAddress((void**)&wdh, g_wdw_h);
    cudaGetSymbolAddress((void**)&wdl, g_wdw_l);
    cudaGetSymbolAddress((void**)&wph, g_wpo_h);
    cudaGetSymbolAddress((void**)&wpl, g_wpo_l);
    cudaGetSymbolAddress((void**)&buf1, g_buf1);
    cudaGetSymbolAddress((void**)&buf2, g_buf2);

    const int smem_bytes = SMEM_WORDS * 4;
    cudaFuncSetAttribute(conv_mma<1, 0>, cudaFuncAttributeMaxDynamicSharedMemorySize, smem_bytes);
    cudaFuncSetAttribute(conv_mma<3, 1>, cudaFuncAttributeMaxDynamicSharedMemorySize, smem_bytes);

    // 1) materialize packed quaternion weights (bf16x2 hi/lo, MMA layout)
    build_weight_pack<<<96, 256>>>(qkv_r, qkv_i, qkv_j, qkv_k, wqh, wql, 96, 32, 1);
    build_weight_pack<<<2592, 256>>>(dw_r, dw_i, dw_j, dw_k, wdh, wdl, 96, 96, 9);
    build_weight_pack<<<32, 256>>>(po_r, po_i, po_j, po_k, wph, wpl, 32, 32, 1);

    // 2) qkv 1x1 conv: [B,128,NSP] -> [B,384,NSP]
    conv_mma<1, 0><<<dim3(NSP / 64, 3, BATCH), 256, smem_bytes>>>(wqh, wql, x, qkv_b, buf1, 384, 128);

    // 3) dw 3x3 conv: [B,384,NSP] -> [B,384,NSP]
    conv_mma<3, 1><<<dim3(NSP / 64, 3, BATCH), 256, smem_bytes>>>(wdh, wdl, buf1, dw_b, buf2, 384, 384);

    // 4) channel attention
    attn_partial<<<dim3(NCHUNK, HEADS, BATCH), 256>>>(buf2);
    attn_finalize<<<dim3(HEADS, BATCH), 32>>>(temp);
    attn_apply<<<dim3(NSP / 256, HEADS, BATCH), 256>>>(buf2, buf1);

    // 5) po 1x1 conv: [B,128,NSP] -> d_out
    conv_mma<1, 0><<<dim3(NSP / 64, 1, BATCH), 256, smem_bytes>>>(wph, wpl, buf1, po_b, out, 128, 128);
}